// round 4
// baseline (speedup 1.0000x reference)
#include <cuda_runtime.h>
#include <cuda_bf16.h>

// ============================================================================
// ECE over N=2^24 samples, 15 bins — single fused kernel.
//   bin(c) = ceil(c*nb) - 1  for c in (0,1], else dropped
//   ece    = sum_b | sum_{i in b} (conf_i - acc_i) | / n
//
// R4: (a) explicit register double-buffering so next batch's 8 LDG.128 issue
// BEFORE this batch's shared-memory chain (R3 paid load latency + chain
// serially); (b) TWO distinct __shared__ bin arrays so the compiler can
// interleave two independent LDS->FADD->STS chains (dynamic-index aliasing
// serialized all 16 updates into one ~590-cycle chain).
// ============================================================================

#define TPB 256
#define MAX_BINS 16          // supports num_bins <= 16 (problem uses 15)
#define NBLOCKS 296          // 2 CTAs/SM * 148 SMs, single wave at occ 2
#define MAX_BLOCKS 4096

__device__ float g_partial[MAX_BLOCKS * MAX_BINS];
__device__ unsigned int g_count = 0;

__device__ __forceinline__ void bin_add(float* __restrict__ sb, int tid,
                                        float cf, float af, float fnb, int nbm1) {
    if (cf > 0.0f && cf <= 1.0f) {
        int b = __float2int_ru(cf * fnb) - 1;   // ceil(c*nb)-1
        b = max(0, min(b, nbm1));
        sb[b * TPB + tid] += cf - af;
    }
}

__global__ __launch_bounds__(TPB)
void ece_kernel(const float* __restrict__ conf,
                const float* __restrict__ acc,
                const int* __restrict__ num_bins_p,
                int n,
                float* __restrict__ out) {
    // Two DISTINCT shared arrays -> provably non-aliasing -> two independent
    // RMW chains the scheduler can interleave.
    __shared__ float sbA[MAX_BINS * TPB];   // 16 KB
    __shared__ float sbB[MAX_BINS * TPB];   // 16 KB
    const int tid = threadIdx.x;
    const int nb = *num_bins_p;
    const float fnb = (float)nb;
    const int nbm1 = nb - 1;

    #pragma unroll
    for (int b = 0; b < MAX_BINS; b++) {
        sbA[b * TPB + tid] = 0.0f;
        sbB[b * TPB + tid] = 0.0f;
    }
    __syncthreads();

    const int nvec = n >> 2;
    const float4* __restrict__ c4 = (const float4*)conf;
    const float4* __restrict__ a4 = (const float4*)acc;
    const int S = gridDim.x * blockDim.x;

    int i = blockIdx.x * blockDim.x + tid;

    float4 c0, c1, c2, c3, a0, a1, a2, a3;
    bool have = (i + 3 * S < nvec);
    if (have) {
        c0 = __ldg(&c4[i]);         c1 = __ldg(&c4[i + S]);
        c2 = __ldg(&c4[i + 2 * S]); c3 = __ldg(&c4[i + 3 * S]);
        a0 = __ldg(&a4[i]);         a1 = __ldg(&a4[i + S]);
        a2 = __ldg(&a4[i + 2 * S]); a3 = __ldg(&a4[i + 3 * S]);
    }
    while (have) {
        const int inext = i + 4 * S;
        const bool have_next = (inext + 3 * S < nvec);
        float4 nc0, nc1, nc2, nc3, na0, na1, na2, na3;
        if (have_next) {            // prefetch NEXT batch before the chain
            nc0 = __ldg(&c4[inext]);         nc1 = __ldg(&c4[inext + S]);
            nc2 = __ldg(&c4[inext + 2 * S]); nc3 = __ldg(&c4[inext + 3 * S]);
            na0 = __ldg(&a4[inext]);         na1 = __ldg(&a4[inext + S]);
            na2 = __ldg(&a4[inext + 2 * S]); na3 = __ldg(&a4[inext + 3 * S]);
        }
        // x,z -> sbA ; y,w -> sbB : two interleavable 8-element chains
        bin_add(sbA, tid, c0.x, a0.x, fnb, nbm1);
        bin_add(sbB, tid, c0.y, a0.y, fnb, nbm1);
        bin_add(sbA, tid, c0.z, a0.z, fnb, nbm1);
        bin_add(sbB, tid, c0.w, a0.w, fnb, nbm1);
        bin_add(sbA, tid, c1.x, a1.x, fnb, nbm1);
        bin_add(sbB, tid, c1.y, a1.y, fnb, nbm1);
        bin_add(sbA, tid, c1.z, a1.z, fnb, nbm1);
        bin_add(sbB, tid, c1.w, a1.w, fnb, nbm1);
        bin_add(sbA, tid, c2.x, a2.x, fnb, nbm1);
        bin_add(sbB, tid, c2.y, a2.y, fnb, nbm1);
        bin_add(sbA, tid, c2.z, a2.z, fnb, nbm1);
        bin_add(sbB, tid, c2.w, a2.w, fnb, nbm1);
        bin_add(sbA, tid, c3.x, a3.x, fnb, nbm1);
        bin_add(sbB, tid, c3.y, a3.y, fnb, nbm1);
        bin_add(sbA, tid, c3.z, a3.z, fnb, nbm1);
        bin_add(sbB, tid, c3.w, a3.w, fnb, nbm1);

        c0 = nc0; c1 = nc1; c2 = nc2; c3 = nc3;
        a0 = na0; a1 = na1; a2 = na2; a3 = na3;
        i = inext;
        have = have_next;
    }
    // vec4 tail (threads whose remaining count < 4 batches)
    for (; i < nvec; i += S) {
        const float4 c = __ldg(&c4[i]);
        const float4 a = __ldg(&a4[i]);
        bin_add(sbA, tid, c.x, a.x, fnb, nbm1);
        bin_add(sbB, tid, c.y, a.y, fnb, nbm1);
        bin_add(sbA, tid, c.z, a.z, fnb, nbm1);
        bin_add(sbB, tid, c.w, a.w, fnb, nbm1);
    }
    // scalar remainder (n not multiple of 4): block 0 only
    if (blockIdx.x == 0) {
        for (int j = (nvec << 2) + tid; j < n; j += blockDim.x) {
            const float cf = conf[j];
            if (cf > 0.0f && cf <= 1.0f) {
                int b = __float2int_ru(cf * fnb) - 1;
                b = max(0, min(b, nbm1));
                sbA[b * TPB + tid] += cf - acc[j];
            }
        }
    }
    __syncthreads();

    // merge B into A (conflict-free), then tree-reduce the 256 lane copies
    #pragma unroll
    for (int b = 0; b < MAX_BINS; b++)
        sbA[b * TPB + tid] += sbB[b * TPB + tid];
    __syncthreads();

    for (int s = TPB / 2; s > 0; s >>= 1) {
        if (tid < s) {
            #pragma unroll
            for (int b = 0; b < MAX_BINS; b++)
                sbA[b * TPB + tid] += sbA[b * TPB + tid + s];
        }
        __syncthreads();
    }

    if (tid < MAX_BINS)
        g_partial[blockIdx.x * MAX_BINS + tid] = sbA[tid * TPB];

    // ---- last-block tail reduction (no second launch) ----
    __shared__ bool is_last;
    __threadfence();
    if (tid == 0) {
        unsigned int ticket = atomicAdd(&g_count, 1u);
        is_last = (ticket == gridDim.x - 1);
    }
    __syncthreads();

    if (is_last) {
        __threadfence();
        // element e -> bin (e & 15); stride 256 keeps bin = tid & 15 constant
        const int total = gridDim.x * MAX_BINS;
        float s = 0.0f;
        for (int e = tid; e < total; e += TPB)
            s += g_partial[e];

        __shared__ float red[TPB];
        red[tid] = s;
        __syncthreads();

        if (tid < MAX_BINS) {
            float t = 0.0f;
            #pragma unroll
            for (int k = 0; k < TPB / MAX_BINS; k++)
                t += red[tid + k * MAX_BINS];
            red[tid] = fabsf(t);     // bins >= nb hold exact zeros
        }
        __syncthreads();

        if (tid == 0) {
            float tot = 0.0f;
            #pragma unroll
            for (int b = 0; b < MAX_BINS; b++)
                tot += red[b];
            out[0] = tot / (float)n;
            g_count = 0;             // reset for next graph replay
        }
    }
}

extern "C" void kernel_launch(void* const* d_in, const int* in_sizes, int n_in,
                              void* d_out, int out_size) {
    const float* conf = (const float*)d_in[0];
    const float* acc  = (const float*)d_in[1];
    const int*   nbp  = (const int*)d_in[2];
    float* out = (float*)d_out;
    const int n = in_sizes[0];

    int nvec = n >> 2;
    int blocks = (nvec + TPB - 1) / TPB;
    if (blocks > NBLOCKS) blocks = NBLOCKS;
    if (blocks < 1) blocks = 1;

    ece_kernel<<<blocks, TPB>>>(conf, acc, nbp, n, out);
}